// round 7
// baseline (speedup 1.0000x reference)
#include <cuda_runtime.h>
#include <cuda_fp16.h>
#include <cstdint>

#define NB 16
#define BC 2048
#define ACH 36    // smem A chunk row stride in floats (144B, 16B-aligned)

// ---------------------------------------------------------------------------
// Scratch (static device globals)
// ---------------------------------------------------------------------------
__device__ float g_base_thorn[BC * 128];
__device__ float g_A1[BC * 128];
__device__ float g_A2[BC * 128];
__device__ float g_thorn_agg[BC * 128];
__device__ float g_clone_agg[BC * 128];
// Prepacked fp16 B fragments for mma.m16n8k16, nt-pairs adjacent.
// 9 matrices: 0=W_thorn[:H], 1=W_clone[:H], 2=W_clone[H:2H],
//             3=W_thorn[H:2H], 4=W_clone[2H:3H], 5..8=W_agg slices.
// layout [m][ ((ks*8 + ntp)*32 + lane)*4 + j ]  -> 8192 u32 per matrix
__device__ uint32_t g_Bpack[9][8192];

// ---------------------------------------------------------------------------
// Prepack all weights into fp16 fragment order.
// ---------------------------------------------------------------------------
__global__ void __launch_bounds__(256) prepack_b_kernel(
    const float* __restrict__ W_thorn,
    const float* __restrict__ W_clone,
    const float* __restrict__ W_agg)
{
    int gidx = blockIdx.x * 256 + threadIdx.x;    // 0 .. 9*8192-1
    int m = gidx >> 13;
    int idx = gidx & 8191;
    const float* W;
    switch (m) {
        case 0: W = W_thorn; break;
        case 1: W = W_clone; break;
        case 2: W = W_clone + 16384; break;
        case 3: W = W_thorn + 16384; break;
        case 4: W = W_clone + 32768; break;
        default: W = W_agg + (m - 5) * 16384; break;
    }
    int j    = idx & 3;
    int lane = (idx >> 2) & 31;
    int ntp  = (idx >> 7) & 7;
    int ks   = idx >> 10;
    int t4 = lane & 3, g = lane >> 2;
    int nt = 2 * ntp + (j >> 1);
    int k = ks * 16 + (j & 1) * 8 + 2 * t4;
    int n = nt * 8 + g;
    __half2 h = __floats2half2_rn(W[k * 128 + n], W[(k + 1) * 128 + n]);
    g_Bpack[m][idx] = *(uint32_t*)&h;
}

// ---------------------------------------------------------------------------
// MMA helpers
// ---------------------------------------------------------------------------
__device__ __forceinline__ void mma2(const uint4& bb,
                                     uint32_t a0, uint32_t a1, uint32_t a2, uint32_t a3,
                                     float* acc0, float* acc1) {
    asm volatile(
        "mma.sync.aligned.m16n8k16.row.col.f32.f16.f16.f32 "
        "{%0,%1,%2,%3}, {%4,%5,%6,%7}, {%8,%9}, {%0,%1,%2,%3};"
        : "+f"(acc0[0]), "+f"(acc0[1]), "+f"(acc0[2]), "+f"(acc0[3])
        : "r"(a0), "r"(a1), "r"(a2), "r"(a3), "r"(bb.x), "r"(bb.y));
    asm volatile(
        "mma.sync.aligned.m16n8k16.row.col.f32.f16.f16.f32 "
        "{%0,%1,%2,%3}, {%4,%5,%6,%7}, {%8,%9}, {%0,%1,%2,%3};"
        : "+f"(acc1[0]), "+f"(acc1[1]), "+f"(acc1[2]), "+f"(acc1[3])
        : "r"(a0), "r"(a1), "r"(a2), "r"(a3), "r"(bb.z), "r"(bb.w));
}

// Warp-level K=128 GEMM accumulate, A read directly from gmem (small kernels).
__device__ __forceinline__ void mma_acc_k128(
    const float* __restrict__ A0,
    const uint32_t* __restrict__ Bp,
    float acc[16][4], int lane)
{
    const int g = lane >> 2, t4 = lane & 3;
    const float* p0 = A0 + g * 128 + 2 * t4;
    const float* p1 = A0 + (g + 8) * 128 + 2 * t4;
    float2 f00 = *(const float2*)(p0);
    float2 f10 = *(const float2*)(p1);
    float2 f01 = *(const float2*)(p0 + 8);
    float2 f11 = *(const float2*)(p1 + 8);
#pragma unroll
    for (int ks = 0; ks < 8; ks++) {
        __half2 h;
        uint32_t a0, a1, a2, a3;
        h = __floats2half2_rn(f00.x, f00.y); a0 = *(uint32_t*)&h;
        h = __floats2half2_rn(f10.x, f10.y); a1 = *(uint32_t*)&h;
        h = __floats2half2_rn(f01.x, f01.y); a2 = *(uint32_t*)&h;
        h = __floats2half2_rn(f11.x, f11.y); a3 = *(uint32_t*)&h;
        if (ks < 7) {
            f00 = *(const float2*)(p0 + 16 * (ks + 1));
            f10 = *(const float2*)(p1 + 16 * (ks + 1));
            f01 = *(const float2*)(p0 + 16 * (ks + 1) + 8);
            f11 = *(const float2*)(p1 + 16 * (ks + 1) + 8);
        }
        const uint32_t* bbase = Bp + ks * 1024 + lane * 4;
#pragma unroll
        for (int ntp = 0; ntp < 8; ntp++) {
            uint4 bb = *(const uint4*)&bbase[ntp * 128];
            mma2(bb, a0, a1, a2, a3, acc[2 * ntp], acc[2 * ntp + 1]);
        }
    }
}

__device__ __forceinline__ void zero_acc(float acc[16][4]) {
#pragma unroll
    for (int nt = 0; nt < 16; nt++)
#pragma unroll
        for (int c = 0; c < 4; c++) acc[nt][c] = 0.0f;
}

__device__ __forceinline__ void cp_async16(uint32_t dst, const float* src) {
    asm volatile("cp.async.cg.shared.global [%0], [%1], 16;"
                 :: "r"(dst), "l"(__cvta_generic_to_global(src)));
}

// ---------------------------------------------------------------------------
// Precompute: clone @ {W_thorn[:H], W_clone[:H], W_clone[H:2H]}
// ---------------------------------------------------------------------------
__global__ void __launch_bounds__(128) precompute_kernel(
    const float* __restrict__ clone)
{
    const int tid = threadIdx.x;
    const int warp = tid >> 5;
    const int lane = tid & 31;
    const int y = blockIdx.y;
    const int m0 = blockIdx.x * 64 + warp * 16;

    float* out = (y == 0) ? g_base_thorn : (y == 1) ? g_A1 : g_A2;

    float acc[16][4];
    zero_acc(acc);
    mma_acc_k128(clone + (size_t)m0 * 128, g_Bpack[y], acc, lane);

    const int g = lane >> 2, t4 = lane & 3;
    const int r0 = m0 + g, r1 = r0 + 8;
#pragma unroll
    for (int nt = 0; nt < 16; nt++) {
        const int n0 = nt * 8 + 2 * t4;
        *(float2*)&out[(size_t)r0 * 128 + n0] = make_float2(acc[nt][0], acc[nt][1]);
        *(float2*)&out[(size_t)r1 * 128 + n0] = make_float2(acc[nt][2], acc[nt][3]);
    }
}

// ---------------------------------------------------------------------------
// Relation kernel: one block per (bc, branch). 256 threads = 8 warps.
// A staged fp32 via cp.async double-buffered 32-col chunks; MMA overlaps
// the next chunk's global loads.
// ---------------------------------------------------------------------------
__global__ void __launch_bounds__(256) relation_mma_kernel(
    const float* __restrict__ thorn_rel,
    const float* __restrict__ clone_rel,
    const float* __restrict__ b_thorn,
    const float* __restrict__ b_clone,
    const int* __restrict__ thorn_mask,
    const int* __restrict__ clone_mask)
{
    __shared__ __align__(16) float sAbuf[2][128 * ACH];   // 36864 B
    __shared__ float red[8 * 128];

    const int tid = threadIdx.x;
    const int warp = tid >> 5;
    const int lane = tid & 31;
    const int g = lane >> 2;
    const int t4 = lane & 3;
    const int wrow = warp * 16;
    const int bc = blockIdx.x;
    const int branch = blockIdx.y;
    const int b = bc >> 7;

    const float* rel = branch ? clone_rel : thorn_rel;
    const float* bias = branch ? b_clone : b_thorn;
    const int* mask = branch ? clone_mask : thorn_mask;
    const float* baseCol = branch ? g_A1 : g_base_thorn;
    float* out = branch ? g_clone_agg : g_thorn_agg;
    const uint32_t* __restrict__ Bp = g_Bpack[3 + branch];

    const float* Atile = rel + (size_t)bc * 16384;

    // smem u32 base addresses of the two buffers
    uint32_t sb0, sb1;
    asm("{ .reg .u64 t; cvta.to.shared.u64 t, %1; cvt.u32.u64 %0, t; }"
        : "=r"(sb0) : "l"((const void*)sAbuf[0]));
    asm("{ .reg .u64 t; cvta.to.shared.u64 t, %1; cvt.u32.u64 %0, t; }"
        : "=r"(sb1) : "l"((const void*)sAbuf[1]));

    // Per-thread staging mapping: 4 x 16B per chunk.
    const int srow = tid >> 1;            // base rows tid/2 (+64)
    // idx = tid + r*256: row = idx>>3? Use direct: idx covers 0..1023,
    // row = idx >> 3 (0..127), q = idx & 7 (16B unit within 128B row).
    auto stage = [&](int ch, uint32_t sbase) {
#pragma unroll
        for (int r = 0; r < 4; r++) {
            int idx = tid + r * 256;
            int row = idx >> 3;
            int q = idx & 7;
            cp_async16(sbase + (uint32_t)(row * ACH + q * 4) * 4,
                       Atile + (size_t)row * 128 + ch * 32 + q * 4);
        }
        asm volatile("cp.async.commit_group;");
    };
    (void)srow;

    float acc[16][4];
    zero_acc(acc);

    stage(0, sb0);
    stage(1, sb1);

#pragma unroll
    for (int ch = 0; ch < 4; ch++) {
        if (ch < 3) asm volatile("cp.async.wait_group 1;");
        else        asm volatile("cp.async.wait_group 0;");
        __syncthreads();

        const float* buf = sAbuf[ch & 1];
#pragma unroll
        for (int ksl = 0; ksl < 2; ksl++) {
            const int ks = ch * 2 + ksl;
            float2 f00 = *(const float2*)&buf[(wrow + g) * ACH + ksl * 16 + 2 * t4];
            float2 f10 = *(const float2*)&buf[(wrow + g + 8) * ACH + ksl * 16 + 2 * t4];
            float2 f01 = *(const float2*)&buf[(wrow + g) * ACH + ksl * 16 + 2 * t4 + 8];
            float2 f11 = *(const float2*)&buf[(wrow + g + 8) * ACH + ksl * 16 + 2 * t4 + 8];
            __half2 h;
            uint32_t a0, a1, a2, a3;
            h = __floats2half2_rn(f00.x, f00.y); a0 = *(uint32_t*)&h;
            h = __floats2half2_rn(f10.x, f10.y); a1 = *(uint32_t*)&h;
            h = __floats2half2_rn(f01.x, f01.y); a2 = *(uint32_t*)&h;
            h = __floats2half2_rn(f11.x, f11.y); a3 = *(uint32_t*)&h;
            const uint32_t* bbase = Bp + ks * 1024 + lane * 4;
#pragma unroll
            for (int ntp = 0; ntp < 8; ntp++) {
                uint4 bb = *(const uint4*)&bbase[ntp * 128];
                mma2(bb, a0, a1, a2, a3, acc[2 * ntp], acc[2 * ntp + 1]);
            }
        }

        if (ch < 2) {
            __syncthreads();                 // all warps done reading buf[ch&1]
            stage(ch + 2, (ch & 1) ? sb1 : sb0);
        }
    }

    // Epilogue: rows r0 = wrow+g, r1 = r0+8; cols n0 = nt*8 + 2*t4.
    const int r0 = wrow + g;
    const int r1 = r0 + 8;
    const float m0 = (float)mask[b * 128 + r0];
    const float m1 = (float)mask[b * 128 + r1];
    const float* rt0p = g_A2 + ((size_t)(b * 128 + r0)) * 128;
    const float* rt1p = g_A2 + ((size_t)(b * 128 + r1)) * 128;

#pragma unroll
    for (int nt = 0; nt < 16; nt++) {
        const int n0 = nt * 8 + 2 * t4;
        float2 bs = *(const float2*)&baseCol[(size_t)bc * 128 + n0];
        float2 bi = *(const float2*)&bias[n0];
        float add0 = bs.x + bi.x;
        float add1 = bs.y + bi.y;
        float x00 = acc[nt][0] + add0;
        float x01 = acc[nt][1] + add1;
        float x10 = acc[nt][2] + add0;
        float x11 = acc[nt][3] + add1;
        if (branch) {
            float2 rt0 = *(const float2*)&rt0p[n0];
            float2 rt1 = *(const float2*)&rt1p[n0];
            x00 += rt0.x; x01 += rt0.y;
            x10 += rt1.x; x11 += rt1.y;
        }
        float c0 = fmaxf(fmaxf(x00, 0.0f) * m0, fmaxf(x10, 0.0f) * m1);
        float c1 = fmaxf(fmaxf(x01, 0.0f) * m0, fmaxf(x11, 0.0f) * m1);
#pragma unroll
        for (int off = 4; off < 32; off <<= 1) {
            c0 = fmaxf(c0, __shfl_xor_sync(0xFFFFFFFFu, c0, off));
            c1 = fmaxf(c1, __shfl_xor_sync(0xFFFFFFFFu, c1, off));
        }
        if (g == 0) {
            red[warp * 128 + n0] = c0;
            red[warp * 128 + n0 + 1] = c1;
        }
    }

    __syncthreads();
    if (tid < 128) {
        float m = 0.0f;
#pragma unroll
        for (int w = 0; w < 8; w++) m = fmaxf(m, red[w * 128 + tid]);
        out[(size_t)bc * 128 + tid] = m;
    }
}

// ---------------------------------------------------------------------------
// Fused final: out = clone + relu([clone|food|thorn_agg|clone_agg] @ W_agg + b)
// Grid 128, 128 threads = 4 warps; warp w computes K-slice w for the block's
// 16 rows, partials summed through smem.
// ---------------------------------------------------------------------------
__global__ void __launch_bounds__(128) final_kernel(
    const float* __restrict__ clone,
    const float* __restrict__ food,
    const float* __restrict__ b_agg,
    float* __restrict__ out)
{
    __shared__ float sacc[4][16 * 128];

    const int tid = threadIdx.x;
    const int warp = tid >> 5;
    const int lane = tid & 31;
    const int m0 = blockIdx.x * 16;

    const float* src = (warp == 0) ? clone : (warp == 1) ? food
                     : (warp == 2) ? g_thorn_agg : g_clone_agg;

    float acc[16][4];
    zero_acc(acc);
    mma_acc_k128(src + (size_t)m0 * 128, g_Bpack[5 + warp], acc, lane);

    const int g = lane >> 2, t4 = lane & 3;
#pragma unroll
    for (int nt = 0; nt < 16; nt++) {
        const int n0 = nt * 8 + 2 * t4;
        *(float2*)&sacc[warp][g * 128 + n0]       = make_float2(acc[nt][0], acc[nt][1]);
        *(float2*)&sacc[warp][(g + 8) * 128 + n0] = make_float2(acc[nt][2], acc[nt][3]);
    }
    __syncthreads();

#pragma unroll
    for (int i = 0; i < 16; i++) {
        int e = tid + i * 128;            // 0..2047
        int r = e >> 7, n = e & 127;
        float s = sacc[0][e] + sacc[1][e] + sacc[2][e] + sacc[3][e] + b_agg[n];
        size_t o = (size_t)(m0 + r) * 128 + n;
        out[o] = clone[o] + fmaxf(s, 0.0f);
    }
}

// ---------------------------------------------------------------------------
// Launch
// ---------------------------------------------------------------------------
extern "C" void kernel_launch(void* const* d_in, const int* in_sizes, int n_in,
                              void* d_out, int out_size)
{
    const float* food       = (const float*)d_in[0];
    const float* thorn_rel  = (const float*)d_in[1];
    const float* clone      = (const float*)d_in[2];
    const float* clone_rel  = (const float*)d_in[3];
    const int*   thorn_mask = (const int*)d_in[4];
    const int*   clone_mask = (const int*)d_in[5];
    const float* W_thorn    = (const float*)d_in[6];
    const float* b_thorn    = (const float*)d_in[7];
    const float* W_clone    = (const float*)d_in[8];
    const float* b_clone    = (const float*)d_in[9];
    const float* W_agg      = (const float*)d_in[10];
    const float* b_agg      = (const float*)d_in[11];
    float* out = (float*)d_out;

    prepack_b_kernel<<<288, 256>>>(W_thorn, W_clone, W_agg);
    precompute_kernel<<<dim3(32, 3), 128>>>(clone);
    relation_mma_kernel<<<dim3(BC, 2), 256>>>(thorn_rel, clone_rel,
                                              b_thorn, b_clone,
                                              thorn_mask, clone_mask);
    final_kernel<<<128, 128>>>(clone, food, b_agg, out);
}

// round 8
// speedup vs baseline: 1.3592x; 1.3592x over previous
#include <cuda_runtime.h>
#include <cuda_fp16.h>
#include <cstdint>

#define NB 16
#define BC 2048
#define WSTRIDE 272   // bytes per A row in a warp's smem region (256 data + 16 pad)

// ---------------------------------------------------------------------------
// Scratch (static device globals)
// ---------------------------------------------------------------------------
__device__ float g_base_thorn[BC * 128];
__device__ float g_A1[BC * 128];
__device__ float g_A2[BC * 128];
__device__ float g_thorn_agg[BC * 128];
__device__ float g_clone_agg[BC * 128];
// Prepacked fp16 B fragments for mma.m16n8k16, nt-pairs adjacent.
// 9 matrices: 0=W_thorn[:H], 1=W_clone[:H], 2=W_clone[H:2H],
//             3=W_thorn[H:2H], 4=W_clone[2H:3H], 5..8=W_agg slices.
// layout [m][ ((ks*8 + ntp)*32 + lane)*4 + j ]  -> 8192 u32 per matrix
__device__ uint32_t g_Bpack[9][8192];

// ---------------------------------------------------------------------------
// Prepack all weights into fp16 fragment order.
// ---------------------------------------------------------------------------
__global__ void __launch_bounds__(256) prepack_b_kernel(
    const float* __restrict__ W_thorn,
    const float* __restrict__ W_clone,
    const float* __restrict__ W_agg)
{
    int gidx = blockIdx.x * 256 + threadIdx.x;    // 0 .. 9*8192-1
    int m = gidx >> 13;
    int idx = gidx & 8191;
    const float* W;
    switch (m) {
        case 0: W = W_thorn; break;
        case 1: W = W_clone; break;
        case 2: W = W_clone + 16384; break;
        case 3: W = W_thorn + 16384; break;
        case 4: W = W_clone + 32768; break;
        default: W = W_agg + (m - 5) * 16384; break;
    }
    int j    = idx & 3;
    int lane = (idx >> 2) & 31;
    int ntp  = (idx >> 7) & 7;
    int ks   = idx >> 10;
    int t4 = lane & 3, g = lane >> 2;
    int nt = 2 * ntp + (j >> 1);
    int k = ks * 16 + (j & 1) * 8 + 2 * t4;
    int n = nt * 8 + g;
    __half2 h = __floats2half2_rn(W[k * 128 + n], W[(k + 1) * 128 + n]);
    g_Bpack[m][idx] = *(uint32_t*)&h;
}

// ---------------------------------------------------------------------------
// MMA helpers
// ---------------------------------------------------------------------------
__device__ __forceinline__ void mma2(const uint4& bb,
                                     uint32_t a0, uint32_t a1, uint32_t a2, uint32_t a3,
                                     float* acc0, float* acc1) {
    asm volatile(
        "mma.sync.aligned.m16n8k16.row.col.f32.f16.f16.f32 "
        "{%0,%1,%2,%3}, {%4,%5,%6,%7}, {%8,%9}, {%0,%1,%2,%3};"
        : "+f"(acc0[0]), "+f"(acc0[1]), "+f"(acc0[2]), "+f"(acc0[3])
        : "r"(a0), "r"(a1), "r"(a2), "r"(a3), "r"(bb.x), "r"(bb.y));
    asm volatile(
        "mma.sync.aligned.m16n8k16.row.col.f32.f16.f16.f32 "
        "{%0,%1,%2,%3}, {%4,%5,%6,%7}, {%8,%9}, {%0,%1,%2,%3};"
        : "+f"(acc1[0]), "+f"(acc1[1]), "+f"(acc1[2]), "+f"(acc1[3])
        : "r"(a0), "r"(a1), "r"(a2), "r"(a3), "r"(bb.z), "r"(bb.w));
}

// Warp-level K=128 GEMM accumulate, A read directly from gmem (small kernels).
__device__ __forceinline__ void mma_acc_k128(
    const float* __restrict__ A0,
    const uint32_t* __restrict__ Bp,
    float acc[16][4], int lane)
{
    const int g = lane >> 2, t4 = lane & 3;
    const float* p0 = A0 + g * 128 + 2 * t4;
    const float* p1 = A0 + (g + 8) * 128 + 2 * t4;
    float2 f00 = *(const float2*)(p0);
    float2 f10 = *(const float2*)(p1);
    float2 f01 = *(const float2*)(p0 + 8);
    float2 f11 = *(const float2*)(p1 + 8);
#pragma unroll
    for (int ks = 0; ks < 8; ks++) {
        __half2 h;
        uint32_t a0, a1, a2, a3;
        h = __floats2half2_rn(f00.x, f00.y); a0 = *(uint32_t*)&h;
        h = __floats2half2_rn(f10.x, f10.y); a1 = *(uint32_t*)&h;
        h = __floats2half2_rn(f01.x, f01.y); a2 = *(uint32_t*)&h;
        h = __floats2half2_rn(f11.x, f11.y); a3 = *(uint32_t*)&h;
        if (ks < 7) {
            f00 = *(const float2*)(p0 + 16 * (ks + 1));
            f10 = *(const float2*)(p1 + 16 * (ks + 1));
            f01 = *(const float2*)(p0 + 16 * (ks + 1) + 8);
            f11 = *(const float2*)(p1 + 16 * (ks + 1) + 8);
        }
        const uint32_t* bbase = Bp + ks * 1024 + lane * 4;
#pragma unroll
        for (int ntp = 0; ntp < 8; ntp++) {
            uint4 bb = *(const uint4*)&bbase[ntp * 128];
            mma2(bb, a0, a1, a2, a3, acc[2 * ntp], acc[2 * ntp + 1]);
        }
    }
}

__device__ __forceinline__ void zero_acc(float acc[16][4]) {
#pragma unroll
    for (int nt = 0; nt < 16; nt++)
#pragma unroll
        for (int c = 0; c < 4; c++) acc[nt][c] = 0.0f;
}

// ---------------------------------------------------------------------------
// Precompute: clone @ {W_thorn[:H], W_clone[:H], W_clone[H:2H]}
// ---------------------------------------------------------------------------
__global__ void __launch_bounds__(128) precompute_kernel(
    const float* __restrict__ clone)
{
    const int tid = threadIdx.x;
    const int warp = tid >> 5;
    const int lane = tid & 31;
    const int y = blockIdx.y;
    const int m0 = blockIdx.x * 64 + warp * 16;

    float* out = (y == 0) ? g_base_thorn : (y == 1) ? g_A1 : g_A2;

    float acc[16][4];
    zero_acc(acc);
    mma_acc_k128(clone + (size_t)m0 * 128, g_Bpack[y], acc, lane);

    const int g = lane >> 2, t4 = lane & 3;
    const int r0 = m0 + g, r1 = r0 + 8;
#pragma unroll
    for (int nt = 0; nt < 16; nt++) {
        const int n0 = nt * 8 + 2 * t4;
        *(float2*)&out[(size_t)r0 * 128 + n0] = make_float2(acc[nt][0], acc[nt][1]);
        *(float2*)&out[(size_t)r1 * 128 + n0] = make_float2(acc[nt][2], acc[nt][3]);
    }
}

// ---------------------------------------------------------------------------
// Relation kernel: one block per (bc, branch). 256 threads = 8 warps.
// WARP-PRIVATE staging: each warp loads its own 16 A rows (16 LDG.128/lane
// burst), converts to fp16 in its private smem region, __syncwarp only,
// then ldmatrix + MMA. No block barrier between staging and compute, so
// warps free-run and DRAM overlaps tensor work.
// ---------------------------------------------------------------------------
__global__ void __launch_bounds__(256) relation_mma_kernel(
    const float* __restrict__ thorn_rel,
    const float* __restrict__ clone_rel,
    const float* __restrict__ b_thorn,
    const float* __restrict__ b_clone,
    const int* __restrict__ thorn_mask,
    const int* __restrict__ clone_mask)
{
    __shared__ __align__(16) char sA[8][16 * WSTRIDE];   // 34816 B
    __shared__ float red[8 * 128];

    const int tid = threadIdx.x;
    const int warp = tid >> 5;
    const int lane = tid & 31;
    const int g = lane >> 2;
    const int t4 = lane & 3;
    const int wrow = warp * 16;
    const int bc = blockIdx.x;
    const int branch = blockIdx.y;
    const int b = bc >> 7;

    const float* rel = branch ? clone_rel : thorn_rel;
    const float* bias = branch ? b_clone : b_thorn;
    const int* mask = branch ? clone_mask : thorn_mask;
    const float* baseCol = branch ? g_A1 : g_base_thorn;
    float* out = branch ? g_clone_agg : g_thorn_agg;
    const uint32_t* __restrict__ Bp = g_Bpack[3 + branch];

    char* wsA = sA[warp];

    // Stage this warp's 16 rows: lane loads float4 #lane of each row.
    const float4* Arow = (const float4*)(rel + (size_t)bc * 16384 + (size_t)wrow * 128);
#pragma unroll
    for (int i = 0; i < 16; i++) {
        float4 v = Arow[i * 32 + lane];
        __half2 h01 = __floats2half2_rn(v.x, v.y);
        __half2 h23 = __floats2half2_rn(v.z, v.w);
        *(uint2*)&wsA[i * WSTRIDE + lane * 8] =
            make_uint2(*(uint32_t*)&h01, *(uint32_t*)&h23);
    }
    __syncwarp();

    // ldmatrix base address (u32 shared-space) for this lane.
    uint32_t wsA_u32;
    asm("{ .reg .u64 t; cvta.to.shared.u64 t, %1; cvt.u32.u64 %0, t; }"
        : "=r"(wsA_u32) : "l"((const void*)wsA));
    const int mi = lane >> 3;       // matrix index 0..3
    const int lr = lane & 7;        // row within 8x8 matrix
    const int arow = (mi & 1) * 8 + lr;          // row within warp's 16
    const int acolh = (mi >> 1) * 8;             // half-elem column offset
    uint32_t lm_addr = wsA_u32 + arow * WSTRIDE + acolh * 2;

    float acc[16][4];
    zero_acc(acc);

#pragma unroll
    for (int ks = 0; ks < 8; ks++) {
        uint32_t a0, a1, a2, a3;
        asm volatile("ldmatrix.sync.aligned.m8n8.x4.shared.b16 {%0,%1,%2,%3}, [%4];"
                     : "=r"(a0), "=r"(a1), "=r"(a2), "=r"(a3)
                     : "r"(lm_addr + ks * 32));
        const uint32_t* bbase = Bp + ks * 1024 + lane * 4;
#pragma unroll
        for (int ntp = 0; ntp < 8; ntp++) {
            uint4 bb = *(const uint4*)&bbase[ntp * 128];
            mma2(bb, a0, a1, a2, a3, acc[2 * ntp], acc[2 * ntp + 1]);
        }
    }

    // Epilogue: rows r0 = wrow+g, r1 = r0+8; cols n0 = nt*8 + 2*t4.
    const int r0 = wrow + g;
    const int r1 = r0 + 8;
    const float m0 = (float)mask[b * 128 + r0];
    const float m1 = (float)mask[b * 128 + r1];
    const float* rt0p = g_A2 + ((size_t)(b * 128 + r0)) * 128;
    const float* rt1p = g_A2 + ((size_t)(b * 128 + r1)) * 128;

#pragma unroll
    for (int nt = 0; nt < 16; nt++) {
        const int n0 = nt * 8 + 2 * t4;
        float2 bs = *(const float2*)&baseCol[(size_t)bc * 128 + n0];
        float2 bi = *(const float2*)&bias[n0];
        float add0 = bs.x + bi.x;
        float add1 = bs.y + bi.y;
        float x00 = acc[nt][0] + add0;
        float x01 = acc[nt][1] + add1;
        float x10 = acc[nt][2] + add0;
        float x11 = acc[nt][3] + add1;
        if (branch) {
            float2 rt0 = *(const float2*)&rt0p[n0];
            float2 rt1 = *(const float2*)&rt1p[n0];
            x00 += rt0.x; x01 += rt0.y;
            x10 += rt1.x; x11 += rt1.y;
        }
        float c0 = fmaxf(fmaxf(x00, 0.0f) * m0, fmaxf(x10, 0.0f) * m1);
        float c1 = fmaxf(fmaxf(x01, 0.0f) * m0, fmaxf(x11, 0.0f) * m1);
#pragma unroll
        for (int off = 4; off < 32; off <<= 1) {
            c0 = fmaxf(c0, __shfl_xor_sync(0xFFFFFFFFu, c0, off));
            c1 = fmaxf(c1, __shfl_xor_sync(0xFFFFFFFFu, c1, off));
        }
        if (g == 0) {
            red[warp * 128 + n0] = c0;
            red[warp * 128 + n0 + 1] = c1;
        }
    }

    __syncthreads();
    if (tid < 128) {
        float m = 0.0f;
#pragma unroll
        for (int w = 0; w < 8; w++) m = fmaxf(m, red[w * 128 + tid]);
        out[(size_t)bc * 128 + tid] = m;
    }
}

// ---------------------------------------------------------------------------
// Fused final: out = clone + relu([clone|food|thorn_agg|clone_agg] @ W_agg + b)
// Grid 128, 128 threads = 4 warps; warp w computes K-slice w for the block's
// 16 rows, partials summed through smem.
// ---------------------------------------------------------------------------
__global__ void __launch_bounds__(128) final_kernel(
    const float* __restrict__ clone,
    const float* __restrict__ food,
    const float* __restrict__ b_agg,
    float* __restrict__ out)
{
    __shared__ float sacc[4][16 * 128];

    const int tid = threadIdx.x;
    const int warp = tid >> 5;
    const int lane = tid & 31;
    const int m0 = blockIdx.x * 16;

    const float* src = (warp == 0) ? clone : (warp == 1) ? food
                     : (warp == 2) ? g_thorn_agg : g_clone_agg;

    float acc[16][4];
    zero_acc(acc);
    mma_acc_k128(src + (size_t)m0 * 128, g_Bpack[5 + warp], acc, lane);

    const int g = lane >> 2, t4 = lane & 3;
#pragma unroll
    for (int nt = 0; nt < 16; nt++) {
        const int n0 = nt * 8 + 2 * t4;
        *(float2*)&sacc[warp][g * 128 + n0]       = make_float2(acc[nt][0], acc[nt][1]);
        *(float2*)&sacc[warp][(g + 8) * 128 + n0] = make_float2(acc[nt][2], acc[nt][3]);
    }
    __syncthreads();

#pragma unroll
    for (int i = 0; i < 16; i++) {
        int e = tid + i * 128;            // 0..2047
        int r = e >> 7, n = e & 127;
        float s = sacc[0][e] + sacc[1][e] + sacc[2][e] + sacc[3][e] + b_agg[n];
        size_t o = (size_t)(m0 + r) * 128 + n;
        out[o] = clone[o] + fmaxf(s, 0.0f);
    }
}

// ---------------------------------------------------------------------------
// Launch
// ---------------------------------------------------------------------------
extern "C" void kernel_launch(void* const* d_in, const int* in_sizes, int n_in,
                              void* d_out, int out_size)
{
    const float* food       = (const float*)d_in[0];
    const float* thorn_rel  = (const float*)d_in[1];
    const float* clone      = (const float*)d_in[2];
    const float* clone_rel  = (const float*)d_in[3];
    const int*   thorn_mask = (const int*)d_in[4];
    const int*   clone_mask = (const int*)d_in[5];
    const float* W_thorn    = (const float*)d_in[6];
    const float* b_thorn    = (const float*)d_in[7];
    const float* W_clone    = (const float*)d_in[8];
    const float* b_clone    = (const float*)d_in[9];
    const float* W_agg      = (const float*)d_in[10];
    const float* b_agg      = (const float*)d_in[11];
    float* out = (float*)d_out;

    prepack_b_kernel<<<288, 256>>>(W_thorn, W_clone, W_agg);
    precompute_kernel<<<dim3(32, 3), 128>>>(clone);
    relation_mma_kernel<<<dim3(BC, 2), 256>>>(thorn_rel, clone_rel,
                                              b_thorn, b_clone,
                                              thorn_mask, clone_mask);
    final_kernel<<<128, 128>>>(clone, food, b_agg, out);
}

// round 11
// speedup vs baseline: 1.5008x; 1.1042x over previous
#include <cuda_runtime.h>
#include <cuda_fp16.h>
#include <cstdint>

#define NB 16
#define BC 2048
#define WSTRIDE 272   // bytes per A row in smem region (256 data + 16 pad)

// ---------------------------------------------------------------------------
// Scratch (static device globals)
// ---------------------------------------------------------------------------
__device__ float g_base_thorn[BC * 128];
__device__ float g_A1[BC * 128];
__device__ float g_A2[BC * 128];
__device__ float g_thorn_agg[BC * 128];
__device__ float g_clone_agg[BC * 128];
// Prepacked fp16 B fragments for mma.m16n8k16, nt-pairs adjacent.
// 9 matrices: 0=W_thorn[:H], 1=W_clone[:H], 2=W_clone[H:2H],
//             3=W_thorn[H:2H], 4=W_clone[2H:3H], 5..8=W_agg slices.
// layout [m][ ((ks*8 + ntp)*32 + lane)*4 + j ]  -> 8192 u32 per matrix
__device__ uint32_t g_Bpack[9][8192];

// ---------------------------------------------------------------------------
// Prepack all weights into fp16 fragment order.
// ---------------------------------------------------------------------------
__global__ void __launch_bounds__(256) prepack_b_kernel(
    const float* __restrict__ W_thorn,
    const float* __restrict__ W_clone,
    const float* __restrict__ W_agg)
{
    int gidx = blockIdx.x * 256 + threadIdx.x;    // 0 .. 9*8192-1
    int m = gidx >> 13;
    int idx = gidx & 8191;
    const float* W;
    switch (m) {
        case 0: W = W_thorn; break;
        case 1: W = W_clone; break;
        case 2: W = W_clone + 16384; break;
        case 3: W = W_thorn + 16384; break;
        case 4: W = W_clone + 32768; break;
        default: W = W_agg + (m - 5) * 16384; break;
    }
    int j    = idx & 3;
    int lane = (idx >> 2) & 31;
    int ntp  = (idx >> 7) & 7;
    int ks   = idx >> 10;
    int t4 = lane & 3, g = lane >> 2;
    int nt = 2 * ntp + (j >> 1);
    int k = ks * 16 + (j & 1) * 8 + 2 * t4;
    int n = nt * 8 + g;
    __half2 h = __floats2half2_rn(W[k * 128 + n], W[(k + 1) * 128 + n]);
    g_Bpack[m][idx] = *(uint32_t*)&h;
}

// ---------------------------------------------------------------------------
// MMA helpers
// ---------------------------------------------------------------------------
__device__ __forceinline__ void mma2(const uint4& bb,
                                     uint32_t a0, uint32_t a1, uint32_t a2, uint32_t a3,
                                     float* acc0, float* acc1) {
    asm volatile(
        "mma.sync.aligned.m16n8k16.row.col.f32.f16.f16.f32 "
        "{%0,%1,%2,%3}, {%4,%5,%6,%7}, {%8,%9}, {%0,%1,%2,%3};"
        : "+f"(acc0[0]), "+f"(acc0[1]), "+f"(acc0[2]), "+f"(acc0[3])
        : "r"(a0), "r"(a1), "r"(a2), "r"(a3), "r"(bb.x), "r"(bb.y));
    asm volatile(
        "mma.sync.aligned.m16n8k16.row.col.f32.f16.f16.f32 "
        "{%0,%1,%2,%3}, {%4,%5,%6,%7}, {%8,%9}, {%0,%1,%2,%3};"
        : "+f"(acc1[0]), "+f"(acc1[1]), "+f"(acc1[2]), "+f"(acc1[3])
        : "r"(a0), "r"(a1), "r"(a2), "r"(a3), "r"(bb.z), "r"(bb.w));
}

// Warp-level GEMM accumulate over ks steps [ks0, ks0+nks), A fp32 in gmem.
__device__ __forceinline__ void mma_acc_gmem(
    const float* __restrict__ A0,      // warp's first row; k offset ks0*16
    const uint32_t* __restrict__ Bp,
    float acc[16][4], int lane, int ks0, int nks)
{
    const int g = lane >> 2, t4 = lane & 3;
    const float* p0 = A0 + g * 128 + ks0 * 16 + 2 * t4;
    const float* p1 = A0 + (g + 8) * 128 + ks0 * 16 + 2 * t4;
    float2 f00 = *(const float2*)(p0);
    float2 f10 = *(const float2*)(p1);
    float2 f01 = *(const float2*)(p0 + 8);
    float2 f11 = *(const float2*)(p1 + 8);
#pragma unroll
    for (int kk = 0; kk < 8; kk++) {
        if (kk >= nks) break;
        __half2 h;
        uint32_t a0, a1, a2, a3;
        h = __floats2half2_rn(f00.x, f00.y); a0 = *(uint32_t*)&h;
        h = __floats2half2_rn(f10.x, f10.y); a1 = *(uint32_t*)&h;
        h = __floats2half2_rn(f01.x, f01.y); a2 = *(uint32_t*)&h;
        h = __floats2half2_rn(f11.x, f11.y); a3 = *(uint32_t*)&h;
        if (kk + 1 < nks) {
            f00 = *(const float2*)(p0 + 16 * (kk + 1));
            f10 = *(const float2*)(p1 + 16 * (kk + 1));
            f01 = *(const float2*)(p0 + 16 * (kk + 1) + 8);
            f11 = *(const float2*)(p1 + 16 * (kk + 1) + 8);
        }
        const uint32_t* bbase = Bp + (ks0 + kk) * 1024 + lane * 4;
#pragma unroll
        for (int ntp = 0; ntp < 8; ntp++) {
            uint4 bb = *(const uint4*)&bbase[ntp * 128];
            mma2(bb, a0, a1, a2, a3, acc[2 * ntp], acc[2 * ntp + 1]);
        }
    }
}

__device__ __forceinline__ void zero16(float acc[16][4]) {
#pragma unroll
    for (int nt = 0; nt < 16; nt++)
#pragma unroll
        for (int c = 0; c < 4; c++) acc[nt][c] = 0.0f;
}

// ---------------------------------------------------------------------------
// Precompute: clone @ {W_thorn[:H], W_clone[:H], W_clone[H:2H]}
// ---------------------------------------------------------------------------
__global__ void __launch_bounds__(128) precompute_kernel(
    const float* __restrict__ clone)
{
    const int tid = threadIdx.x;
    const int warp = tid >> 5;
    const int lane = tid & 31;
    const int y = blockIdx.y;
    const int m0 = blockIdx.x * 64 + warp * 16;

    float* out = (y == 0) ? g_base_thorn : (y == 1) ? g_A1 : g_A2;

    float acc[16][4];
    zero16(acc);
    mma_acc_gmem(clone + (size_t)m0 * 128, g_Bpack[y], acc, lane, 0, 8);

    const int g = lane >> 2, t4 = lane & 3;
    const int r0 = m0 + g, r1 = r0 + 8;
#pragma unroll
    for (int nt = 0; nt < 16; nt++) {
        const int n0 = nt * 8 + 2 * t4;
        *(float2*)&out[(size_t)r0 * 128 + n0] = make_float2(acc[nt][0], acc[nt][1]);
        *(float2*)&out[(size_t)r1 * 128 + n0] = make_float2(acc[nt][2], acc[nt][3]);
    }
}

// ---------------------------------------------------------------------------
// Relation kernel: one block per (bc, branch). 256 threads = 8 warps.
// Warp tiling 32 rows x 64 cols: warp w -> p = w&3 (rows p*32..+32),
// cg = w>>2 (cols cg*64..+64). Warps p and p+4 share smem region p; each
// stages 16 of the 32 rows, pair-synced with named barrier p+1 (no block
// barrier before compute). B fragment loads halved vs 16x128 tiling.
// ---------------------------------------------------------------------------
__global__ void __launch_bounds__(256) relation_mma_kernel(
    const float* __restrict__ thorn_rel,
    const float* __restrict__ clone_rel,
    const float* __restrict__ b_thorn,
    const float* __restrict__ b_clone,
    const int* __restrict__ thorn_mask,
    const int* __restrict__ clone_mask)
{
    __shared__ __align__(16) char sA[4][32 * WSTRIDE];   // 34816 B
    __shared__ float red[8 * 128];

    const int tid = threadIdx.x;
    const int warp = tid >> 5;
    const int lane = tid & 31;
    const int g = lane >> 2;
    const int t4 = lane & 3;
    const int p  = warp & 3;        // row group: rows p*32..p*32+32
    const int cg = warp >> 2;       // col group: cols cg*64..cg*64+64
    const int bc = blockIdx.x;
    const int branch = blockIdx.y;
    const int b = bc >> 7;

    const float* rel = branch ? clone_rel : thorn_rel;
    const float* bias = branch ? b_clone : b_thorn;
    const int* mask = branch ? clone_mask : thorn_mask;
    const float* baseCol = branch ? g_A1 : g_base_thorn;
    float* out = branch ? g_clone_agg : g_thorn_agg;
    const uint32_t* __restrict__ Bp = g_Bpack[3 + branch];

    char* reg = sA[p];

    // Stage: this warp loads 16 rows (local rows cg*16..cg*16+16 of region p).
    {
        const int lrow0 = cg * 16;
        const float4* Arow = (const float4*)(rel + (size_t)bc * 16384
                                             + (size_t)(p * 32 + lrow0) * 128);
#pragma unroll
        for (int i = 0; i < 16; i++) {
            float4 v = Arow[i * 32 + lane];
            __half2 h01 = __floats2half2_rn(v.x, v.y);
            __half2 h23 = __floats2half2_rn(v.z, v.w);
            *(uint2*)&reg[(lrow0 + i) * WSTRIDE + lane * 8] =
                make_uint2(*(uint32_t*)&h01, *(uint32_t*)&h23);
        }
    }
    // Pair-local named barrier (warps p and p+4), 64 threads.
    asm volatile("bar.sync %0, 64;" :: "r"(p + 1) : "memory");

    // ldmatrix addresses for the two 16-row tiles of region p.
    uint32_t reg_u32;
    asm("{ .reg .u64 t; cvta.to.shared.u64 t, %1; cvt.u32.u64 %0, t; }"
        : "=r"(reg_u32) : "l"((const void*)reg));
    const int mi = lane >> 3;
    const int lr = lane & 7;
    const int arow = (mi & 1) * 8 + lr;
    const int acolh = (mi >> 1) * 8;
    uint32_t lm0 = reg_u32 + arow * WSTRIDE + acolh * 2;
    uint32_t lm1 = lm0 + 16 * WSTRIDE;

    // acc[mt][nt][c]: mt 0/1 row tiles, nt 0..7 col tiles (cols cg*64+nt*8)
    float acc[2][8][4];
#pragma unroll
    for (int mt = 0; mt < 2; mt++)
#pragma unroll
        for (int nt = 0; nt < 8; nt++)
#pragma unroll
            for (int c = 0; c < 4; c++) acc[mt][nt][c] = 0.0f;

#pragma unroll
    for (int ks = 0; ks < 8; ks++) {
        uint32_t a00, a01, a02, a03, a10, a11, a12, a13;
        asm volatile("ldmatrix.sync.aligned.m8n8.x4.shared.b16 {%0,%1,%2,%3}, [%4];"
                     : "=r"(a00), "=r"(a01), "=r"(a02), "=r"(a03)
                     : "r"(lm0 + ks * 32));
        asm volatile("ldmatrix.sync.aligned.m8n8.x4.shared.b16 {%0,%1,%2,%3}, [%4];"
                     : "=r"(a10), "=r"(a11), "=r"(a12), "=r"(a13)
                     : "r"(lm1 + ks * 32));
        const uint32_t* bbase = Bp + ks * 1024 + (cg * 4) * 128 + lane * 4;
#pragma unroll
        for (int ntp = 0; ntp < 4; ntp++) {
            uint4 bb = *(const uint4*)&bbase[ntp * 128];
            mma2(bb, a00, a01, a02, a03, acc[0][2 * ntp], acc[0][2 * ntp + 1]);
            mma2(bb, a10, a11, a12, a13, acc[1][2 * ntp], acc[1][2 * ntp + 1]);
        }
    }

    // Epilogue. Warp rows: wr + mt*16 + g and +8; cols: c0 + nt*8 + 2*t4.
    const int wr = p * 32;
    const int c0 = cg * 64;
    int rowi[4] = {wr + g, wr + g + 8, wr + 16 + g, wr + 24 + g};
    float mk[4];
    const float* rtp[4];
#pragma unroll
    for (int q = 0; q < 4; q++) {
        mk[q] = (float)mask[b * 128 + rowi[q]];
        rtp[q] = g_A2 + ((size_t)(b * 128 + rowi[q])) * 128;
    }

#pragma unroll
    for (int nt = 0; nt < 8; nt++) {
        const int n0 = c0 + nt * 8 + 2 * t4;
        float2 bs = *(const float2*)&baseCol[(size_t)bc * 128 + n0];
        float2 bi = *(const float2*)&bias[n0];
        float add0 = bs.x + bi.x;
        float add1 = bs.y + bi.y;
        float c0m = 0.0f, c1m = 0.0f;
#pragma unroll
        for (int mt = 0; mt < 2; mt++) {
            float x0 = acc[mt][nt][0] + add0;
            float x1 = acc[mt][nt][1] + add1;
            float x2 = acc[mt][nt][2] + add0;
            float x3 = acc[mt][nt][3] + add1;
            if (branch) {
                float2 ra = *(const float2*)&rtp[mt * 2][n0];
                float2 rb = *(const float2*)&rtp[mt * 2 + 1][n0];
                x0 += ra.x; x1 += ra.y;
                x2 += rb.x; x3 += rb.y;
            }
            float ma = mk[mt * 2], mb = mk[mt * 2 + 1];
            c0m = fmaxf(c0m, fmaxf(fmaxf(x0, 0.0f) * ma, fmaxf(x2, 0.0f) * mb));
            c1m = fmaxf(c1m, fmaxf(fmaxf(x1, 0.0f) * ma, fmaxf(x3, 0.0f) * mb));
        }
#pragma unroll
        for (int off = 4; off < 32; off <<= 1) {
            c0m = fmaxf(c0m, __shfl_xor_sync(0xFFFFFFFFu, c0m, off));
            c1m = fmaxf(c1m, __shfl_xor_sync(0xFFFFFFFFu, c1m, off));
        }
        if (g == 0) {
            red[warp * 128 + n0] = c0m;
            red[warp * 128 + n0 + 1] = c1m;
        }
    }

    __syncthreads();
    if (tid < 128) {
        // Column tid served by warps with cg == tid>>6, i.e. w = (tid>>6)*4 + 0..3
        int wb = (tid >> 6) * 4;
        float m = fmaxf(fmaxf(red[(wb + 0) * 128 + tid], red[(wb + 1) * 128 + tid]),
                        fmaxf(red[(wb + 2) * 128 + tid], red[(wb + 3) * 128 + tid]));
        out[(size_t)bc * 128 + tid] = m;
    }
}

// ---------------------------------------------------------------------------
// Fused final: out = clone + relu([clone|food|thorn_agg|clone_agg] @ W_agg + b)
// Grid 128, 256 threads = 8 warps; warp w handles slice s = w>>1,
// K-half kh = w&1. kh=0 warps write sacc[s], kh=1 warps add into it
// (two-phase, 32 KB smem total), then block-wide sum of 4 buffers.
// ---------------------------------------------------------------------------
__global__ void __launch_bounds__(256) final_kernel(
    const float* __restrict__ clone,
    const float* __restrict__ food,
    const float* __restrict__ b_agg,
    float* __restrict__ out)
{
    __shared__ float sacc[4][16 * 128];     // 32 KB

    const int tid = threadIdx.x;
    const int warp = tid >> 5;
    const int lane = tid & 31;
    const int m0 = blockIdx.x * 16;
    const int s = warp >> 1;
    const int kh = warp & 1;

    const float* src = (s == 0) ? clone : (s == 1) ? food
                     : (s == 2) ? g_thorn_agg : g_clone_agg;

    float acc[16][4];
    zero16(acc);
    mma_acc_gmem(src + (size_t)m0 * 128, g_Bpack[5 + s], acc, lane, kh * 4, 4);

    const int g = lane >> 2, t4 = lane & 3;
    if (kh == 0) {
#pragma unroll
        for (int nt = 0; nt < 16; nt++) {
            const int n0 = nt * 8 + 2 * t4;
            *(float2*)&sacc[s][g * 128 + n0]       = make_float2(acc[nt][0], acc[nt][1]);
            *(float2*)&sacc[s][(g + 8) * 128 + n0] = make_float2(acc[nt][2], acc[nt][3]);
        }
    }
    __syncthreads();
    if (kh == 1) {
#pragma unroll
        for (int nt = 0; nt < 16; nt++) {
            const int n0 = nt * 8 + 2 * t4;
            float2 u0 = *(float2*)&sacc[s][g * 128 + n0];
            float2 u1 = *(float2*)&sacc[s][(g + 8) * 128 + n0];
            u0.x += acc[nt][0]; u0.y += acc[nt][1];
            u1.x += acc[nt][2]; u1.y += acc[nt][3];
            *(float2*)&sacc[s][g * 128 + n0]       = u0;
            *(float2*)&sacc[s][(g + 8) * 128 + n0] = u1;
        }
    }
    __syncthreads();

#pragma unroll
    for (int i = 0; i < 8; i++) {
        int e = tid + i * 256;            // 0..2047
        int r = e >> 7, n = e & 127;
        float ssum = sacc[0][e] + sacc[1][e] + sacc[2][e] + sacc[3][e] + b_agg[n];
        size_t o = (size_t)(m0 + r) * 128 + n;
        out[o] = clone[o] + fmaxf(ssum, 0.0f);
    }
}

// ---------------------------------------------------------------------------
// Launch
// ---------------------------------------------------------------------------
extern "C" void kernel_launch(void* const* d_in, const int* in_sizes, int n_in,
                              void* d_out, int out_size)
{
    const float* food       = (const float*)d_in[0];
    const float* thorn_rel  = (const float*)d_in[1];
    const float* clone      = (const float*)d_in[2];
    const float* clone_rel  = (const float*)d_in[3];
    const int*   thorn_mask = (const int*)d_in[4];
    const int*   clone_mask = (const int*)d_in[5];
    const float* W_thorn    = (const float*)d_in[6];
    const float* b_thorn    = (const float*)d_in[7];
    const float* W_clone    = (const float*)d_in[8];
    const float* b_clone    = (const float*)d_in[9];
    const float* W_agg      = (const float*)d_in[10];
    const float* b_agg      = (const float*)d_in[11];
    float* out = (float*)d_out;

    prepack_b_kernel<<<288, 256>>>(W_thorn, W_clone, W_agg);
    precompute_kernel<<<dim3(32, 3), 128>>>(clone);
    relation_mma_kernel<<<dim3(BC, 2), 256>>>(thorn_rel, clone_rel,
                                              b_thorn, b_clone,
                                              thorn_mask, clone_mask);
    final_kernel<<<128, 256>>>(clone, food, b_agg, out);
}